// round 14
// baseline (speedup 1.0000x reference)
#include <cuda_runtime.h>
#include <cuda_fp16.h>
#include <cstdint>
#include <math.h>

// x: [B, I, K] = [32, 2048, 16]
// W: [1, I, J, D, K] = [1, 2048, 64, 32, 16]
// v: [B, J, D] = [32, 64, 32]
#define BB   32
#define II   2048
#define KK   16
#define JJ   64
#define DD   32
#define JD   (JJ * DD)        // 2048

// fused u_hat + pass0 tiling
#define ICH  16               // i's per chunk
#define NCH  (II / ICH)       // 128 chunks (spart stride)
#define PSL  256              // p's per slice
#define NSL  (JD / PSL)       // 8 slices

// pass12 chunking
#define NCH12 32
#define IPC  (II / NCH12)     // 64
#define RR   4                // rows per pipeline step
#define STEPS (IPC / RR)      // 16

__device__ __half g_uhat[(size_t)II * BB * JD];     // [i][b][p] fp16 (256 MB)
__device__ float  g_spart[(size_t)BB * NCH * JD];   // [b][128][p] fp32 (32 MB)
__device__ float  g_v[BB * JD];                     // current v
__device__ float  g_vsum[BB * JD];                  // v0 + v1 (logit linearity)

// ---------------- cp.async helpers (pass12 only) ----------------
__device__ __forceinline__ void cp_async16(void* smem_ptr, const void* gptr) {
    unsigned int saddr = (unsigned int)__cvta_generic_to_shared(smem_ptr);
    asm volatile("cp.async.cg.shared.global [%0], [%1], 16;\n" :: "r"(saddr), "l"(gptr));
}
__device__ __forceinline__ void cp_commit() {
    asm volatile("cp.async.commit_group;\n" ::: "memory");
}
template <int N>
__device__ __forceinline__ void cp_wait() {
    asm volatile("cp.async.wait_group %0;\n" :: "n"(N) : "memory");
}

// ---------------- packed f32x2 helpers ----------------
__device__ __forceinline__ unsigned long long f32x2_mul(unsigned long long a,
                                                        unsigned long long b) {
    unsigned long long d;
    asm("mul.rn.f32x2 %0, %1, %2;" : "=l"(d) : "l"(a), "l"(b));
    return d;
}
__device__ __forceinline__ unsigned long long f32x2_fma(unsigned long long a,
                                                        unsigned long long b,
                                                        unsigned long long c) {
    unsigned long long d;
    asm("fma.rn.f32x2 %0, %1, %2, %3;" : "=l"(d) : "l"(a), "l"(b), "l"(c));
    return d;
}
__device__ __forceinline__ float f32x2_hsum(unsigned long long a) {
    float lo, hi;
    asm("mov.b64 {%0, %1}, %2;" : "=f"(lo), "=f"(hi) : "l"(a));
    return lo + hi;
}

// ---------------------------------------------------------------------------
// Fused K1 + pass0 (direct LDG for W, x staged once, no cp.async):
//   u_hat[i][b][p] = sum_k W[i,p,k] * x[b,i,k]     (fp16 store)
//   spart[b][ch][p] = sum_{i in ch} u_hat (fp32)   (uniform-c partials)
// CTA = (slice of 256 p, chunk of 16 consecutive i).
// Thread owns p = slice*256 + pg*4 + r (r=0..3), b = bg*8 .. bg*8+7.
// ---------------------------------------------------------------------------
__global__ void __launch_bounds__(256) k_uhat_fused(const float* __restrict__ x,
                                                    const float* __restrict__ W) {
    const int slice = blockIdx.x;        // 0..7
    const int ch    = blockIdx.y;        // 0..127
    const int tid   = threadIdx.x;
    const int pg    = tid & 63;
    const int bg    = tid >> 6;
    const int b0    = bg * 8;
    const int i0    = ch * ICH;

    // x[b, i0..i0+15, :] staged once: [(b*16 + ii)*4 + c] ulonglong2 (32 KB)
    __shared__ ulonglong2 xsm[BB * ICH * 4];

    const uint4* x4 = reinterpret_cast<const uint4*>(x);
    for (int t = tid; t < BB * ICH * 4; t += 256) {
        const int b  = t >> 6;           // 16 i x 4 chunks = 64 contiguous chunks per b
        const int r6 = t & 63;
        const uint4 raw = x4[(size_t)(b * II + i0) * 4 + r6];
        xsm[t] = *reinterpret_cast<const ulonglong2*>(&raw);
    }
    __syncthreads();

    float s[4][8];
    #pragma unroll
    for (int r = 0; r < 4; ++r)
        #pragma unroll
        for (int bl = 0; bl < 8; ++bl) s[r][bl] = 0.f;

    const ulonglong2* W2 = reinterpret_cast<const ulonglong2*>(W);

    for (int ii = 0; ii < ICH; ++ii) {
        const int i = i0 + ii;

        // my 4 W rows (p = slice*256 + pg*4 + r), 16 x LDG.128
        const ulonglong2* wrow = W2 + ((size_t)i * JD + slice * PSL + pg * 4) * 4;
        ulonglong2 w2[4][4];
        #pragma unroll
        for (int r = 0; r < 4; ++r)
            #pragma unroll
            for (int c = 0; c < 4; ++c)
                w2[r][c] = wrow[r * 4 + c];

        __half* outi = g_uhat + (size_t)i * (BB * JD);

        #pragma unroll 2
        for (int bl = 0; bl < 8; ++bl) {
            const int b = b0 + bl;
            ulonglong2 xv[4];
            #pragma unroll
            for (int c = 0; c < 4; ++c) xv[c] = xsm[(b * ICH + ii) * 4 + c];  // broadcast

            float u[4];
            #pragma unroll
            for (int r = 0; r < 4; ++r) {
                unsigned long long acc = f32x2_mul(w2[r][0].x, xv[0].x);
                acc = f32x2_fma(w2[r][0].y, xv[0].y, acc);
                acc = f32x2_fma(w2[r][1].x, xv[1].x, acc);
                acc = f32x2_fma(w2[r][1].y, xv[1].y, acc);
                acc = f32x2_fma(w2[r][2].x, xv[2].x, acc);
                acc = f32x2_fma(w2[r][2].y, xv[2].y, acc);
                acc = f32x2_fma(w2[r][3].x, xv[3].x, acc);
                acc = f32x2_fma(w2[r][3].y, xv[3].y, acc);
                u[r] = f32x2_hsum(acc);
                s[r][bl] += u[r];
            }
            __half2 h0 = __floats2half2_rn(u[0], u[1]);
            __half2 h1 = __floats2half2_rn(u[2], u[3]);
            uint2 pack;
            pack.x = *reinterpret_cast<unsigned int*>(&h0);
            pack.y = *reinterpret_cast<unsigned int*>(&h1);
            reinterpret_cast<uint2*>(outi + (size_t)b * JD)[slice * 64 + pg] = pack;
        }
    }

    // uniform-c partials (fp32)
    #pragma unroll
    for (int bl = 0; bl < 8; ++bl) {
        const int b = b0 + bl;
        float4* sp = reinterpret_cast<float4*>(g_spart + ((size_t)b * NCH + ch) * JD);
        sp[slice * 64 + pg] = make_float4(s[0][bl], s[1][bl], s[2][bl], s[3][bl]);
    }
}

// ---------------------------------------------------------------------------
// Passes 1 & 2: register-resident u rows, double-buffered cp.async.
// Agreement logits vs g_v (pass 1) or g_vsum = v0+v1 (pass 2, useVsum=1).
// Thread t owns halves 8t..8t+7 of every row (single j = t>>2).
// grid: (B, NCH12), 256 threads.
// ---------------------------------------------------------------------------
__global__ void __launch_bounds__(256, 4) k_pass12(int useVsum) {
    const int b   = blockIdx.x;
    const int ch  = blockIdx.y;
    const int tid = threadIdx.x;
    const int r   = tid >> 6;    // softmax-space row (0..3)
    const int j   = tid & 63;    // softmax-space capsule
    const int wid = tid >> 5;

    __shared__ uint4  ub[2][RR][256];      // 2 x 4 rows x 4KB fp16 (32 KB)
    __shared__ float  lg[JJ * 5];          // [j*5 + rr], padded stride
    __shared__ float  cs[RR][JJ];          // normalized coeffs
    __shared__ float2 ms[8];               // per-warp (max, sum)

    const float* vsrc = useVsum ? g_vsum : g_v;
    float vf[8];
    {
        const float4* gv4 = reinterpret_cast<const float4*>(vsrc + (size_t)b * JD);
        const float4 v0 = gv4[2 * tid], v1 = gv4[2 * tid + 1];
        vf[0] = v0.x; vf[1] = v0.y; vf[2] = v0.z; vf[3] = v0.w;
        vf[4] = v1.x; vf[5] = v1.y; vf[6] = v1.z; vf[7] = v1.w;
    }

    float s[8];
    #pragma unroll
    for (int q = 0; q < 8; ++q) s[q] = 0.f;

    const uint4* grow0 = reinterpret_cast<const uint4*>(
        g_uhat + (size_t)(ch * IPC) * (BB * JD) + (size_t)b * JD);
    const size_t gstride = (size_t)BB * JD / 8;   // uint4 per i row

    #pragma unroll
    for (int rr = 0; rr < RR; ++rr)
        cp_async16(&ub[0][rr][tid], grow0 + (size_t)rr * gstride + tid);
    cp_commit();
    #pragma unroll
    for (int rr = 0; rr < RR; ++rr)
        cp_async16(&ub[1][rr][tid], grow0 + (size_t)(RR + rr) * gstride + tid);
    cp_commit();

    for (int st = 0; st < STEPS; ++st) {
        if (st == STEPS - 1) cp_wait<0>(); else cp_wait<1>();
        const int buf = st & 1;

        uint4 u4[RR];
        #pragma unroll
        for (int rr = 0; rr < RR; ++rr) u4[rr] = ub[buf][rr][tid];

        if (st + 2 < STEPS) {
            const uint4* gr = grow0 + (size_t)(st + 2) * RR * gstride;
            #pragma unroll
            for (int rr = 0; rr < RR; ++rr)
                cp_async16(&ub[buf][rr][tid], gr + (size_t)rr * gstride + tid);
            cp_commit();
        }

        // ---- agreement: per-thread 8-FMA partial dot + quad reduce ----
        float a[RR];
        #pragma unroll
        for (int rr = 0; rr < RR; ++rr) {
            const __half2* h = reinterpret_cast<const __half2*>(&u4[rr]);
            float acc = 0.f;
            #pragma unroll
            for (int m = 0; m < 4; ++m) {
                const float2 f = __half22float2(h[m]);
                acc += f.x * vf[2 * m] + f.y * vf[2 * m + 1];
            }
            acc += __shfl_xor_sync(0xffffffffu, acc, 1);
            acc += __shfl_xor_sync(0xffffffffu, acc, 2);
            a[rr] = acc;
        }
        lg[(tid >> 2) * 5 + (tid & 3)] = a[tid & 3];
        __syncthreads();

        // ---- softmax in (r, j) space ----
        const float araw = lg[j * 5 + r];

        float mw = araw;
        #pragma unroll
        for (int o = 16; o > 0; o >>= 1)
            mw = fmaxf(mw, __shfl_xor_sync(0xffffffffu, mw, o));
        const float e = __expf(araw - mw);
        float sw = e;
        #pragma unroll
        for (int o = 16; o > 0; o >>= 1)
            sw += __shfl_xor_sync(0xffffffffu, sw, o);
        if ((tid & 31) == 0) ms[wid] = make_float2(mw, sw);
        __syncthreads();
        {
            const float2 other = ms[wid ^ 1];
            const float M = fmaxf(mw, other.x);
            const float S = sw * __expf(mw - M) + other.y * __expf(other.x - M);
            cs[r][j] = e * __expf(mw - M) / S;
        }
        __syncthreads();

        // ---- weighted accumulate from registers ----
        #pragma unroll
        for (int rr = 0; rr < RR; ++rr) {
            const float c = cs[rr][tid >> 2];
            const __half2* h = reinterpret_cast<const __half2*>(&u4[rr]);
            #pragma unroll
            for (int m = 0; m < 4; ++m) {
                const float2 f = __half22float2(h[m]);
                s[2 * m]     += c * f.x;
                s[2 * m + 1] += c * f.y;
            }
        }
    }

    // thread t owns p = 8t..8t+7  (float4 store at offset 8t — matches u4 ownership)
    float4* sp = reinterpret_cast<float4*>(g_spart + ((size_t)b * NCH + ch) * JD);
    sp[2 * tid]     = make_float4(s[0], s[1], s[2], s[3]);
    sp[2 * tid + 1] = make_float4(s[4], s[5], s[6], s[7]);
}

// ---------------------------------------------------------------------------
// Squash: one 32-thread block per (b,j). Sums nch chunk partials.
// mode 0: g_v = v, g_vsum = v ; mode 1: g_vsum += v ; mode 2: out = v
// ---------------------------------------------------------------------------
__global__ void k_squash(float prescale, int mode, int nch, float* __restrict__ out) {
    const int row = blockIdx.x;          // b*64 + j
    const int d   = threadIdx.x;
    const int b   = row >> 6;
    const int j   = row & 63;

    const float* sp = g_spart + (size_t)b * NCH * JD + j * 32 + d;
    float sv = 0.f;
    #pragma unroll 8
    for (int ch = 0; ch < nch; ++ch) sv += sp[(size_t)ch * JD];
    sv *= prescale;

    float sq = sv * sv;
    #pragma unroll
    for (int o = 16; o > 0; o >>= 1) sq += __shfl_xor_sync(0xffffffffu, sq, o);

    const float scale = sq / (1.f + sq);
    const float v = scale * sv / sqrtf(sq + 1e-8f);

    const int idx = row * 32 + d;
    if (mode == 0)      { g_v[idx] = v; g_vsum[idx] = v; }
    else if (mode == 1) { g_vsum[idx] += v; }
    else                { out[idx] = v; }
}

// ---------------------------------------------------------------------------
extern "C" void kernel_launch(void* const* d_in, const int* in_sizes, int n_in,
                              void* d_out, int out_size) {
    (void)n_in; (void)out_size;
    const float* x = (const float*)d_in[0];
    const float* W = (const float*)d_in[1];
    if (in_sizes[0] > in_sizes[1]) { const float* t = x; x = W; W = t; }

    float* out = (float*)d_out;

    k_uhat_fused<<<dim3(NSL, NCH), 256>>>(x, W);             // u_hat + s0 partials
    k_squash<<<BB * JJ, 32>>>(1.0f / 64.0f, 0, NCH, nullptr);   // v0 ; vsum = v0

    k_pass12<<<dim3(BB, NCH12), 256>>>(0);                   // logits vs v0
    k_squash<<<BB * JJ, 32>>>(1.0f, 1, NCH12, nullptr);      // vsum = v0+v1

    k_pass12<<<dim3(BB, NCH12), 256>>>(1);                   // logits vs v0+v1
    k_squash<<<BB * JJ, 32>>>(1.0f, 2, NCH12, out);          // v2 -> d_out
}

// round 15
// speedup vs baseline: 1.3991x; 1.3991x over previous
#include <cuda_runtime.h>
#include <cuda_fp16.h>
#include <cstdint>
#include <math.h>

// x: [B, I, K] = [32, 2048, 16]
// W: [1, I, J, D, K] = [1, 2048, 64, 32, 16]
// v: [B, J, D] = [32, 64, 32]
#define BB   32
#define II   2048
#define KK   16
#define JJ   64
#define DD   32
#define JD   (JJ * DD)        // 2048

// fused u_hat + pass0 tiling
#define ICH  16               // i's per chunk
#define NCH  (II / ICH)       // 128 chunks (spart stride)
#define PSL  256              // p's per slice
#define NSL  (JD / PSL)       // 8 slices

// pass12 chunking
#define NCH12 32
#define IPC  (II / NCH12)     // 64
#define RR   4                // rows per pipeline step
#define STEPS (IPC / RR)      // 16

__device__ __half g_uhat[(size_t)II * BB * JD];     // [i][b][p] fp16 (256 MB)
__device__ float  g_spart[(size_t)BB * NCH * JD];   // [b][128][p] fp32 (32 MB)
__device__ float  g_v[BB * JD];                     // current v
__device__ float  g_vsum[BB * JD];                  // v0 + v1 (logit linearity)

// ---------------- cp.async helpers ----------------
__device__ __forceinline__ void cp_async16(void* smem_ptr, const void* gptr) {
    unsigned int saddr = (unsigned int)__cvta_generic_to_shared(smem_ptr);
    asm volatile("cp.async.cg.shared.global [%0], [%1], 16;\n" :: "r"(saddr), "l"(gptr));
}
__device__ __forceinline__ void cp_commit() {
    asm volatile("cp.async.commit_group;\n" ::: "memory");
}
template <int N>
__device__ __forceinline__ void cp_wait() {
    asm volatile("cp.async.wait_group %0;\n" :: "n"(N) : "memory");
}

// ---------------- packed f32x2 helpers ----------------
__device__ __forceinline__ unsigned long long f32x2_mul(unsigned long long a,
                                                        unsigned long long b) {
    unsigned long long d;
    asm("mul.rn.f32x2 %0, %1, %2;" : "=l"(d) : "l"(a), "l"(b));
    return d;
}
__device__ __forceinline__ unsigned long long f32x2_fma(unsigned long long a,
                                                        unsigned long long b,
                                                        unsigned long long c) {
    unsigned long long d;
    asm("fma.rn.f32x2 %0, %1, %2, %3;" : "=l"(d) : "l"(a), "l"(b), "l"(c));
    return d;
}
__device__ __forceinline__ float f32x2_hsum(unsigned long long a) {
    float lo, hi;
    asm("mov.b64 {%0, %1}, %2;" : "=f"(lo), "=f"(hi) : "l"(a));
    return lo + hi;
}

// ---------------------------------------------------------------------------
// Fused K1 + pass0 with cp.async W staging (W read from global exactly once):
//   u_hat[i][b][p] = sum_k W[i,p,k] * x[b,i,k]     (fp16 store)
//   spart[b][ch][p] = sum_{i in ch} u_hat (fp32)   (uniform-c partials)
// CTA = (slice of 256 p, chunk of 16 i). Thread owns p = slice*256 + pg*4 + r
// (r=0..3) and b = bg*8..bg*8+7, with pg = tid&63, bg = tid>>6.
// W staged per-i via cp.async into transposed smem layout [(r*4+c)*64 + pg]
// (reader lane-stride 16B -> conflict-free LDS.128; global stage coalesced).
// ---------------------------------------------------------------------------
__global__ void __launch_bounds__(256) k_uhat_fused(const float* __restrict__ x,
                                                    const float* __restrict__ W) {
    const int slice = blockIdx.x;        // 0..7
    const int ch    = blockIdx.y;        // 0..127
    const int tid   = threadIdx.x;
    const int pg    = tid & 63;
    const int bg    = tid >> 6;
    const int b0    = bg * 8;
    const int i0    = ch * ICH;

    __shared__ ulonglong2 Wsm[2][1024];  // [buf][(r*4+c)*64 + pg]  (16 KB each)
    __shared__ ulonglong2 xsm[2][128];   // [buf][b*4 + c]          (2 KB each)

    const uint4* W4 = reinterpret_cast<const uint4*>(W);
    const uint4* x4 = reinterpret_cast<const uint4*>(x);

    float s[4][8];
    #pragma unroll
    for (int r = 0; r < 4; ++r)
        #pragma unroll
        for (int bl = 0; bl < 8; ++bl) s[r][bl] = 0.f;

    // stage W[i, slice] + x[:, i, :] into buffer d
    #define STAGE(d, i)                                                          \
    do {                                                                         \
        const uint4* wsrc = W4 + ((size_t)(i) * JD + slice * PSL) * 4;           \
        _Pragma("unroll")                                                        \
        for (int q = 0; q < 4; ++q) {                                            \
            const int gi = q * 256 + tid;          /* 0..1023 */                 \
            const int pl = gi >> 2, c = gi & 3;                                  \
            const int sidx = ((pl & 3) * 4 + c) * 64 + (pl >> 2);                \
            cp_async16(&Wsm[d][sidx], wsrc + gi);                                \
        }                                                                        \
        if (tid < 128) {                                                         \
            const int bb = tid >> 2, k4 = tid & 3;                               \
            cp_async16(&xsm[d][tid], x4 + (size_t)(bb * II + (i)) * 4 + k4);     \
        }                                                                        \
        cp_commit();                                                             \
    } while (0)

    STAGE(0, i0);
    STAGE(1, i0 + 1);

    for (int ii = 0; ii < ICH; ++ii) {
        if (ii == ICH - 1) cp_wait<0>(); else cp_wait<1>();
        __syncthreads();
        const int buf = ii & 1;
        const int i   = i0 + ii;

        // my 4 W rows from smem (conflict-free: lane stride = 1 chunk)
        ulonglong2 w2[4][4];
        #pragma unroll
        for (int r = 0; r < 4; ++r)
            #pragma unroll
            for (int c = 0; c < 4; ++c)
                w2[r][c] = Wsm[buf][(r * 4 + c) * 64 + pg];

        __half* outi = g_uhat + (size_t)i * (BB * JD);

        #pragma unroll 2
        for (int bl = 0; bl < 8; ++bl) {
            const int b = b0 + bl;
            ulonglong2 xv[4];
            #pragma unroll
            for (int c = 0; c < 4; ++c) xv[c] = xsm[buf][b * 4 + c];  // broadcast

            float u[4];
            #pragma unroll
            for (int r = 0; r < 4; ++r) {
                unsigned long long acc = f32x2_mul(w2[r][0].x, xv[0].x);
                acc = f32x2_fma(w2[r][0].y, xv[0].y, acc);
                acc = f32x2_fma(w2[r][1].x, xv[1].x, acc);
                acc = f32x2_fma(w2[r][1].y, xv[1].y, acc);
                acc = f32x2_fma(w2[r][2].x, xv[2].x, acc);
                acc = f32x2_fma(w2[r][2].y, xv[2].y, acc);
                acc = f32x2_fma(w2[r][3].x, xv[3].x, acc);
                acc = f32x2_fma(w2[r][3].y, xv[3].y, acc);
                u[r] = f32x2_hsum(acc);
                s[r][bl] += u[r];
            }
            __half2 h0 = __floats2half2_rn(u[0], u[1]);
            __half2 h1 = __floats2half2_rn(u[2], u[3]);
            uint2 pack;
            pack.x = *reinterpret_cast<unsigned int*>(&h0);
            pack.y = *reinterpret_cast<unsigned int*>(&h1);
            reinterpret_cast<uint2*>(outi + (size_t)b * JD)[slice * 64 + pg] = pack;
        }

        __syncthreads();  // all reads of buf done before restage
        if (ii + 2 < ICH) STAGE(buf, i0 + ii + 2);
    }
    #undef STAGE

    // uniform-c partials (fp32)
    #pragma unroll
    for (int bl = 0; bl < 8; ++bl) {
        const int b = b0 + bl;
        float4* sp = reinterpret_cast<float4*>(g_spart + ((size_t)b * NCH + ch) * JD);
        sp[slice * 64 + pg] = make_float4(s[0][bl], s[1][bl], s[2][bl], s[3][bl]);
    }
}

// ---------------------------------------------------------------------------
// Passes 1 & 2: register-resident u rows, double-buffered cp.async.
// Agreement logits vs g_v (pass 1) or g_vsum = v0+v1 (pass 2, useVsum=1).
// Thread t owns halves 8t..8t+7 of every row (single j = t>>2).
// grid: (B, NCH12), 256 threads.
// ---------------------------------------------------------------------------
__global__ void __launch_bounds__(256, 4) k_pass12(int useVsum) {
    const int b   = blockIdx.x;
    const int ch  = blockIdx.y;
    const int tid = threadIdx.x;
    const int r   = tid >> 6;    // softmax-space row (0..3)
    const int j   = tid & 63;    // softmax-space capsule
    const int wid = tid >> 5;

    __shared__ uint4  ub[2][RR][256];      // 2 x 4 rows x 4KB fp16 (32 KB)
    __shared__ float  lg[JJ * 5];          // [j*5 + rr], padded stride
    __shared__ float  cs[RR][JJ];          // normalized coeffs
    __shared__ float2 ms[8];               // per-warp (max, sum)

    const float* vsrc = useVsum ? g_vsum : g_v;
    float vf[8];
    {
        const float4* gv4 = reinterpret_cast<const float4*>(vsrc + (size_t)b * JD);
        const float4 v0 = gv4[2 * tid], v1 = gv4[2 * tid + 1];
        vf[0] = v0.x; vf[1] = v0.y; vf[2] = v0.z; vf[3] = v0.w;
        vf[4] = v1.x; vf[5] = v1.y; vf[6] = v1.z; vf[7] = v1.w;
    }

    float s[8];
    #pragma unroll
    for (int q = 0; q < 8; ++q) s[q] = 0.f;

    const uint4* grow0 = reinterpret_cast<const uint4*>(
        g_uhat + (size_t)(ch * IPC) * (BB * JD) + (size_t)b * JD);
    const size_t gstride = (size_t)BB * JD / 8;   // uint4 per i row

    #pragma unroll
    for (int rr = 0; rr < RR; ++rr)
        cp_async16(&ub[0][rr][tid], grow0 + (size_t)rr * gstride + tid);
    cp_commit();
    #pragma unroll
    for (int rr = 0; rr < RR; ++rr)
        cp_async16(&ub[1][rr][tid], grow0 + (size_t)(RR + rr) * gstride + tid);
    cp_commit();

    for (int st = 0; st < STEPS; ++st) {
        if (st == STEPS - 1) cp_wait<0>(); else cp_wait<1>();
        const int buf = st & 1;

        uint4 u4[RR];
        #pragma unroll
        for (int rr = 0; rr < RR; ++rr) u4[rr] = ub[buf][rr][tid];

        if (st + 2 < STEPS) {
            const uint4* gr = grow0 + (size_t)(st + 2) * RR * gstride;
            #pragma unroll
            for (int rr = 0; rr < RR; ++rr)
                cp_async16(&ub[buf][rr][tid], gr + (size_t)rr * gstride + tid);
            cp_commit();
        }

        // ---- agreement: per-thread 8-FMA partial dot + quad reduce ----
        float a[RR];
        #pragma unroll
        for (int rr = 0; rr < RR; ++rr) {
            const __half2* h = reinterpret_cast<const __half2*>(&u4[rr]);
            float acc = 0.f;
            #pragma unroll
            for (int m = 0; m < 4; ++m) {
                const float2 f = __half22float2(h[m]);
                acc += f.x * vf[2 * m] + f.y * vf[2 * m + 1];
            }
            acc += __shfl_xor_sync(0xffffffffu, acc, 1);
            acc += __shfl_xor_sync(0xffffffffu, acc, 2);
            a[rr] = acc;
        }
        lg[(tid >> 2) * 5 + (tid & 3)] = a[tid & 3];
        __syncthreads();

        // ---- softmax in (r, j) space ----
        const float araw = lg[j * 5 + r];

        float mw = araw;
        #pragma unroll
        for (int o = 16; o > 0; o >>= 1)
            mw = fmaxf(mw, __shfl_xor_sync(0xffffffffu, mw, o));
        const float e = __expf(araw - mw);
        float sw = e;
        #pragma unroll
        for (int o = 16; o > 0; o >>= 1)
            sw += __shfl_xor_sync(0xffffffffu, sw, o);
        if ((tid & 31) == 0) ms[wid] = make_float2(mw, sw);
        __syncthreads();
        {
            const float2 other = ms[wid ^ 1];
            const float M = fmaxf(mw, other.x);
            const float S = sw * __expf(mw - M) + other.y * __expf(other.x - M);
            cs[r][j] = e * __expf(mw - M) / S;
        }
        __syncthreads();

        // ---- weighted accumulate from registers ----
        #pragma unroll
        for (int rr = 0; rr < RR; ++rr) {
            const float c = cs[rr][tid >> 2];
            const __half2* h = reinterpret_cast<const __half2*>(&u4[rr]);
            #pragma unroll
            for (int m = 0; m < 4; ++m) {
                const float2 f = __half22float2(h[m]);
                s[2 * m]     += c * f.x;
                s[2 * m + 1] += c * f.y;
            }
        }
    }

    // thread t owns p = 8t..8t+7 (float4 store at offset 8t — matches u4 ownership)
    float4* sp = reinterpret_cast<float4*>(g_spart + ((size_t)b * NCH + ch) * JD);
    sp[2 * tid]     = make_float4(s[0], s[1], s[2], s[3]);
    sp[2 * tid + 1] = make_float4(s[4], s[5], s[6], s[7]);
}

// ---------------------------------------------------------------------------
// Squash: one 32-thread block per (b,j). Sums nch chunk partials.
// mode 0: g_v = v, g_vsum = v ; mode 1: g_vsum += v ; mode 2: out = v
// ---------------------------------------------------------------------------
__global__ void k_squash(float prescale, int mode, int nch, float* __restrict__ out) {
    const int row = blockIdx.x;          // b*64 + j
    const int d   = threadIdx.x;
    const int b   = row >> 6;
    const int j   = row & 63;

    const float* sp = g_spart + (size_t)b * NCH * JD + j * 32 + d;
    float sv = 0.f;
    #pragma unroll 8
    for (int ch = 0; ch < nch; ++ch) sv += sp[(size_t)ch * JD];
    sv *= prescale;

    float sq = sv * sv;
    #pragma unroll
    for (int o = 16; o > 0; o >>= 1) sq += __shfl_xor_sync(0xffffffffu, sq, o);

    const float scale = sq / (1.f + sq);
    const float v = scale * sv / sqrtf(sq + 1e-8f);

    const int idx = row * 32 + d;
    if (mode == 0)      { g_v[idx] = v; g_vsum[idx] = v; }
    else if (mode == 1) { g_vsum[idx] += v; }
    else                { out[idx] = v; }
}

// ---------------------------------------------------------------------------
extern "C" void kernel_launch(void* const* d_in, const int* in_sizes, int n_in,
                              void* d_out, int out_size) {
    (void)n_in; (void)out_size;
    const float* x = (const float*)d_in[0];
    const float* W = (const float*)d_in[1];
    if (in_sizes[0] > in_sizes[1]) { const float* t = x; x = W; W = t; }

    float* out = (float*)d_out;

    k_uhat_fused<<<dim3(NSL, NCH), 256>>>(x, W);             // u_hat + s0 partials
    k_squash<<<BB * JJ, 32>>>(1.0f / 64.0f, 0, NCH, nullptr);   // v0 ; vsum = v0

    k_pass12<<<dim3(BB, NCH12), 256>>>(0);                   // logits vs v0
    k_squash<<<BB * JJ, 32>>>(1.0f, 1, NCH12, nullptr);      // vsum = v0+v1

    k_pass12<<<dim3(BB, NCH12), 256>>>(1);                   // logits vs v0+v1
    k_squash<<<BB * JJ, 32>>>(1.0f, 2, NCH12, out);          // v2 -> d_out
}

// round 16
// speedup vs baseline: 1.6817x; 1.2020x over previous
#include <cuda_runtime.h>
#include <cuda_fp16.h>
#include <cstdint>
#include <math.h>

// x: [B, I, K] = [32, 2048, 16]
// W: [1, I, J, D, K] = [1, 2048, 64, 32, 16]
// v: [B, J, D] = [32, 64, 32]
#define BB   32
#define II   2048
#define KK   16
#define JJ   64
#define DD   32
#define JD   (JJ * DD)        // 2048
#define NCHUNK 32
#define IPC  (II / NCHUNK)    // 64
#define RR   4                // rows per pipeline step
#define STEPS (IPC / RR)      // 16
#define PSL  256              // p's per slice (uhat)
#define NSL  (JD / PSL)       // 8 slices

__device__ __half g_uhat[(size_t)II * BB * JD];     // [i][b][p] fp16 (256 MB)
__device__ float  g_spart[BB * NCHUNK * JD];        // [b][32][p] fp32
__device__ float  g_v[BB * JD];                     // current v
__device__ float  g_vsum[BB * JD];                  // v0 + v1 (logit linearity)

// ---------------- cp.async helpers ----------------
__device__ __forceinline__ void cp_async16(void* smem_ptr, const void* gptr) {
    unsigned int saddr = (unsigned int)__cvta_generic_to_shared(smem_ptr);
    asm volatile("cp.async.cg.shared.global [%0], [%1], 16;\n" :: "r"(saddr), "l"(gptr));
}
__device__ __forceinline__ void cp_commit() {
    asm volatile("cp.async.commit_group;\n" ::: "memory");
}
template <int N>
__device__ __forceinline__ void cp_wait() {
    asm volatile("cp.async.wait_group %0;\n" :: "n"(N) : "memory");
}

// ---------------- packed f32x2 helpers ----------------
__device__ __forceinline__ unsigned long long f32x2_mul(unsigned long long a,
                                                        unsigned long long b) {
    unsigned long long d;
    asm("mul.rn.f32x2 %0, %1, %2;" : "=l"(d) : "l"(a), "l"(b));
    return d;
}
__device__ __forceinline__ unsigned long long f32x2_fma(unsigned long long a,
                                                        unsigned long long b,
                                                        unsigned long long c) {
    unsigned long long d;
    asm("fma.rn.f32x2 %0, %1, %2, %3;" : "=l"(d) : "l"(a), "l"(b), "l"(c));
    return d;
}
__device__ __forceinline__ float f32x2_hsum(unsigned long long a) {
    float lo, hi;
    asm("mov.b64 {%0, %1}, %2;" : "=f"(lo), "=f"(hi) : "l"(a));
    return lo + hi;
}

// ---------------------------------------------------------------------------
// K1 (staged): u_hat[i][b][p] = sum_k W[i,p,k] * x[b,i,k], fp16 output.
// CTA = (slice of 256 p, one i). W slice (16 KB) staged via coalesced
// cp.async into XOR-swizzled smem:
//   sidx = pg*16 + ((r*4+c) ^ (pg&7))
// Writer: lane-adjacent gi -> consecutive sidx (conflict-free stores).
// Reader: 8-lane phases have distinct (pg&7) -> distinct banks.
// Thread owns p = slice*256 + pg*4 + r (r=0..3), b = bg*8..bg*8+7.
// ---------------------------------------------------------------------------
__global__ void __launch_bounds__(256) k_uhat(const float* __restrict__ x,
                                              const float* __restrict__ W) {
    const int slice = blockIdx.x;        // 0..7
    const int i     = blockIdx.y;        // 0..2047
    const int tid   = threadIdx.x;
    const int pg    = tid & 63;
    const int bg    = tid >> 6;
    const int b0    = bg * 8;

    __shared__ ulonglong2 Wsm[1024];     // swizzled W slice (16 KB)
    __shared__ ulonglong2 xsm[128];      // x[:, i, :] (2 KB)

    const uint4* W4 = reinterpret_cast<const uint4*>(W);
    const uint4* x4 = reinterpret_cast<const uint4*>(x);

    // stage W slice (coalesced global, conflict-free smem)
    {
        const uint4* wsrc = W4 + ((size_t)i * JD + slice * PSL) * 4;
        #pragma unroll
        for (int q = 0; q < 4; ++q) {
            const int gi = q * 256 + tid;                       // 0..1023
            const int sidx = (gi >> 4) * 16 + ((gi & 15) ^ ((gi >> 4) & 7));
            cp_async16(&Wsm[sidx], wsrc + gi);
        }
        if (tid < 128) {
            const int bb = tid >> 2, k4 = tid & 3;
            cp_async16(&xsm[tid], x4 + (size_t)(bb * II + i) * 4 + k4);
        }
        cp_commit();
    }
    cp_wait<0>();
    __syncthreads();

    // my 4 W rows from swizzled smem (conflict-free)
    ulonglong2 w2[4][4];
    #pragma unroll
    for (int r = 0; r < 4; ++r)
        #pragma unroll
        for (int c = 0; c < 4; ++c)
            w2[r][c] = Wsm[pg * 16 + ((r * 4 + c) ^ (pg & 7))];

    __half* outi = g_uhat + (size_t)i * (BB * JD);

    #pragma unroll 2
    for (int bl = 0; bl < 8; ++bl) {
        const int b = b0 + bl;
        ulonglong2 xv[4];
        #pragma unroll
        for (int c = 0; c < 4; ++c) xv[c] = xsm[b * 4 + c];   // broadcast

        float u[4];
        #pragma unroll
        for (int r = 0; r < 4; ++r) {
            unsigned long long acc = f32x2_mul(w2[r][0].x, xv[0].x);
            acc = f32x2_fma(w2[r][0].y, xv[0].y, acc);
            acc = f32x2_fma(w2[r][1].x, xv[1].x, acc);
            acc = f32x2_fma(w2[r][1].y, xv[1].y, acc);
            acc = f32x2_fma(w2[r][2].x, xv[2].x, acc);
            acc = f32x2_fma(w2[r][2].y, xv[2].y, acc);
            acc = f32x2_fma(w2[r][3].x, xv[3].x, acc);
            acc = f32x2_fma(w2[r][3].y, xv[3].y, acc);
            u[r] = f32x2_hsum(acc);
        }
        __half2 h0 = __floats2half2_rn(u[0], u[1]);
        __half2 h1 = __floats2half2_rn(u[2], u[3]);
        uint2 pack;
        pack.x = *reinterpret_cast<unsigned int*>(&h0);
        pack.y = *reinterpret_cast<unsigned int*>(&h1);
        reinterpret_cast<uint2*>(outi + (size_t)b * JD)[slice * 64 + pg] = pack;
    }
}

// ---------------------------------------------------------------------------
// Pass 0: uniform coefficients — chunk partial sums. fp16 in, fp32 out.
// grid: (NCHUNK, B), 256 threads.
// ---------------------------------------------------------------------------
__global__ void __launch_bounds__(256) k_pass0() {
    const int ch  = blockIdx.x;
    const int b   = blockIdx.y;
    const int tid = threadIdx.x;

    float s[8];
    #pragma unroll
    for (int q = 0; q < 8; ++q) s[q] = 0.f;

    const uint4* base = reinterpret_cast<const uint4*>(
        g_uhat + (size_t)(ch * IPC) * (BB * JD) + (size_t)b * JD);
    const size_t stride = (size_t)BB * JD / 8;

    #pragma unroll 8
    for (int ii = 0; ii < IPC; ++ii) {
        const uint4 raw = base[(size_t)ii * stride + tid];
        const __half2* h = reinterpret_cast<const __half2*>(&raw);
        #pragma unroll
        for (int m = 0; m < 4; ++m) {
            const float2 f = __half22float2(h[m]);
            s[2 * m]     += f.x;
            s[2 * m + 1] += f.y;
        }
    }

    float4* sp = reinterpret_cast<float4*>(g_spart + ((size_t)b * NCHUNK + ch) * JD);
    sp[2 * tid]     = make_float4(s[0], s[1], s[2], s[3]);
    sp[2 * tid + 1] = make_float4(s[4], s[5], s[6], s[7]);
}

// ---------------------------------------------------------------------------
// Passes 1 & 2: register-resident u rows, double-buffered cp.async.
// Agreement logits vs g_v (pass 1) or g_vsum = v0+v1 (pass 2, useVsum=1).
// Thread t owns halves 8t..8t+7 of every row (single j = t>>2).
// grid: (B, NCHUNK), 256 threads.
// ---------------------------------------------------------------------------
__global__ void __launch_bounds__(256, 4) k_pass12(int useVsum) {
    const int b   = blockIdx.x;
    const int ch  = blockIdx.y;
    const int tid = threadIdx.x;
    const int r   = tid >> 6;    // softmax-space row (0..3)
    const int j   = tid & 63;    // softmax-space capsule
    const int wid = tid >> 5;

    __shared__ uint4  ub[2][RR][256];      // 2 x 4 rows x 4KB fp16 (32 KB)
    __shared__ float  lg[JJ * 5];          // [j*5 + rr], padded stride
    __shared__ float  cs[RR][JJ];          // normalized coeffs
    __shared__ float2 ms[8];               // per-warp (max, sum)

    const float* vsrc = useVsum ? g_vsum : g_v;
    float vf[8];
    {
        const float4* gv4 = reinterpret_cast<const float4*>(vsrc + (size_t)b * JD);
        const float4 v0 = gv4[2 * tid], v1 = gv4[2 * tid + 1];
        vf[0] = v0.x; vf[1] = v0.y; vf[2] = v0.z; vf[3] = v0.w;
        vf[4] = v1.x; vf[5] = v1.y; vf[6] = v1.z; vf[7] = v1.w;
    }

    float s[8];
    #pragma unroll
    for (int q = 0; q < 8; ++q) s[q] = 0.f;

    const uint4* grow0 = reinterpret_cast<const uint4*>(
        g_uhat + (size_t)(ch * IPC) * (BB * JD) + (size_t)b * JD);
    const size_t gstride = (size_t)BB * JD / 8;   // uint4 per i row

    #pragma unroll
    for (int rr = 0; rr < RR; ++rr)
        cp_async16(&ub[0][rr][tid], grow0 + (size_t)rr * gstride + tid);
    cp_commit();
    #pragma unroll
    for (int rr = 0; rr < RR; ++rr)
        cp_async16(&ub[1][rr][tid], grow0 + (size_t)(RR + rr) * gstride + tid);
    cp_commit();

    for (int st = 0; st < STEPS; ++st) {
        if (st == STEPS - 1) cp_wait<0>(); else cp_wait<1>();
        const int buf = st & 1;

        uint4 u4[RR];
        #pragma unroll
        for (int rr = 0; rr < RR; ++rr) u4[rr] = ub[buf][rr][tid];

        if (st + 2 < STEPS) {
            const uint4* gr = grow0 + (size_t)(st + 2) * RR * gstride;
            #pragma unroll
            for (int rr = 0; rr < RR; ++rr)
                cp_async16(&ub[buf][rr][tid], gr + (size_t)rr * gstride + tid);
            cp_commit();
        }

        // ---- agreement: per-thread 8-FMA partial dot + quad reduce ----
        float a[RR];
        #pragma unroll
        for (int rr = 0; rr < RR; ++rr) {
            const __half2* h = reinterpret_cast<const __half2*>(&u4[rr]);
            float acc = 0.f;
            #pragma unroll
            for (int m = 0; m < 4; ++m) {
                const float2 f = __half22float2(h[m]);
                acc += f.x * vf[2 * m] + f.y * vf[2 * m + 1];
            }
            acc += __shfl_xor_sync(0xffffffffu, acc, 1);
            acc += __shfl_xor_sync(0xffffffffu, acc, 2);
            a[rr] = acc;
        }
        lg[(tid >> 2) * 5 + (tid & 3)] = a[tid & 3];
        __syncthreads();

        // ---- softmax in (r, j) space ----
        const float araw = lg[j * 5 + r];

        float mw = araw;
        #pragma unroll
        for (int o = 16; o > 0; o >>= 1)
            mw = fmaxf(mw, __shfl_xor_sync(0xffffffffu, mw, o));
        const float e = __expf(araw - mw);
        float sw = e;
        #pragma unroll
        for (int o = 16; o > 0; o >>= 1)
            sw += __shfl_xor_sync(0xffffffffu, sw, o);
        if ((tid & 31) == 0) ms[wid] = make_float2(mw, sw);
        __syncthreads();
        {
            const float2 other = ms[wid ^ 1];
            const float M = fmaxf(mw, other.x);
            const float S = sw * __expf(mw - M) + other.y * __expf(other.x - M);
            cs[r][j] = e * __expf(mw - M) / S;
        }
        __syncthreads();

        // ---- weighted accumulate from registers ----
        #pragma unroll
        for (int rr = 0; rr < RR; ++rr) {
            const float c = cs[rr][tid >> 2];
            const __half2* h = reinterpret_cast<const __half2*>(&u4[rr]);
            #pragma unroll
            for (int m = 0; m < 4; ++m) {
                const float2 f = __half22float2(h[m]);
                s[2 * m]     += c * f.x;
                s[2 * m + 1] += c * f.y;
            }
        }
    }

    // thread t owns p = 8t..8t+7 (float4 store at offset 8t)
    float4* sp = reinterpret_cast<float4*>(g_spart + ((size_t)b * NCHUNK + ch) * JD);
    sp[2 * tid]     = make_float4(s[0], s[1], s[2], s[3]);
    sp[2 * tid + 1] = make_float4(s[4], s[5], s[6], s[7]);
}

// ---------------------------------------------------------------------------
// Squash: one 32-thread block per (b,j).
// mode 0: g_v = v, g_vsum = v ; mode 1: g_vsum += v ; mode 2: out = v
// ---------------------------------------------------------------------------
__global__ void k_squash(float prescale, int mode, float* __restrict__ out) {
    const int row = blockIdx.x;          // b*64 + j
    const int d   = threadIdx.x;
    const int b   = row >> 6;
    const int j   = row & 63;

    const float* sp = g_spart + (size_t)b * NCHUNK * JD + j * 32 + d;
    float sv = 0.f;
    #pragma unroll 8
    for (int ch = 0; ch < NCHUNK; ++ch) sv += sp[(size_t)ch * JD];
    sv *= prescale;

    float sq = sv * sv;
    #pragma unroll
    for (int o = 16; o > 0; o >>= 1) sq += __shfl_xor_sync(0xffffffffu, sq, o);

    const float scale = sq / (1.f + sq);
    const float v = scale * sv / sqrtf(sq + 1e-8f);

    const int idx = row * 32 + d;
    if (mode == 0)      { g_v[idx] = v; g_vsum[idx] = v; }
    else if (mode == 1) { g_vsum[idx] += v; }
    else                { out[idx] = v; }
}

// ---------------------------------------------------------------------------
extern "C" void kernel_launch(void* const* d_in, const int* in_sizes, int n_in,
                              void* d_out, int out_size) {
    (void)n_in; (void)out_size;
    const float* x = (const float*)d_in[0];
    const float* W = (const float*)d_in[1];
    if (in_sizes[0] > in_sizes[1]) { const float* t = x; x = W; W = t; }

    float* out = (float*)d_out;

    k_uhat<<<dim3(NSL, II), 256>>>(x, W);

    k_pass0<<<dim3(NCHUNK, BB), 256>>>();
    k_squash<<<BB * JJ, 32>>>(1.0f / 64.0f, 0, nullptr);     // v0 ; vsum = v0

    k_pass12<<<dim3(BB, NCHUNK), 256>>>(0);                  // logits vs v0
    k_squash<<<BB * JJ, 32>>>(1.0f, 1, nullptr);             // vsum = v0+v1

    k_pass12<<<dim3(BB, NCHUNK), 256>>>(1);                  // logits vs v0+v1
    k_squash<<<BB * JJ, 32>>>(1.0f, 2, out);                 // v2 -> d_out
}

// round 17
// speedup vs baseline: 1.7445x; 1.0374x over previous
#include <cuda_runtime.h>
#include <cuda_fp16.h>
#include <cstdint>
#include <math.h>

// x: [B, I, K] = [32, 2048, 16]
// W: [1, I, J, D, K] = [1, 2048, 64, 32, 16]
// v: [B, J, D] = [32, 64, 32]
#define BB   32
#define II   2048
#define KK   16
#define JJ   64
#define DD   32
#define JD   (JJ * DD)        // 2048

// fused u_hat + pass0 tiling
#define ICH  16               // i's per chunk
#define NCH  (II / ICH)       // 128 chunks (spart stride)
#define PSL  256              // p's per slice
#define NSL  (JD / PSL)       // 8 slices

// pass12 chunking
#define NCH12 32
#define IPC  (II / NCH12)     // 64
#define RR   4                // rows per pipeline step
#define STEPS (IPC / RR)      // 16

__device__ __half g_uhat[(size_t)II * BB * JD];     // [i][b][p] fp16 (256 MB)
__device__ float  g_spart[(size_t)BB * NCH * JD];   // [b][128][p] fp32 (32 MB)
__device__ float  g_v[BB * JD];                     // current v
__device__ float  g_vsum[BB * JD];                  // v0 + v1 (logit linearity)

// ---------------- cp.async helpers ----------------
__device__ __forceinline__ void cp_async16(void* smem_ptr, const void* gptr) {
    unsigned int saddr = (unsigned int)__cvta_generic_to_shared(smem_ptr);
    asm volatile("cp.async.cg.shared.global [%0], [%1], 16;\n" :: "r"(saddr), "l"(gptr));
}
__device__ __forceinline__ void cp_commit() {
    asm volatile("cp.async.commit_group;\n" ::: "memory");
}
template <int N>
__device__ __forceinline__ void cp_wait() {
    asm volatile("cp.async.wait_group %0;\n" :: "n"(N) : "memory");
}

// ---------------- packed f32x2 helpers ----------------
__device__ __forceinline__ unsigned long long f32x2_mul(unsigned long long a,
                                                        unsigned long long b) {
    unsigned long long d;
    asm("mul.rn.f32x2 %0, %1, %2;" : "=l"(d) : "l"(a), "l"(b));
    return d;
}
__device__ __forceinline__ unsigned long long f32x2_fma(unsigned long long a,
                                                        unsigned long long b,
                                                        unsigned long long c) {
    unsigned long long d;
    asm("fma.rn.f32x2 %0, %1, %2, %3;" : "=l"(d) : "l"(a), "l"(b), "l"(c));
    return d;
}
__device__ __forceinline__ float f32x2_hsum(unsigned long long a) {
    float lo, hi;
    asm("mov.b64 {%0, %1}, %2;" : "=f"(lo), "=f"(hi) : "l"(a));
    return lo + hi;
}

// ---------------------------------------------------------------------------
// Fused K1 + pass0, double-buffered cp.async W staging, conflict-free swizzle:
//   u_hat[i][b][p] = sum_k W[i,p,k] * x[b,i,k]     (fp16 store)
//   spart[b][ch][p] = sum_{i in ch} u_hat (fp32)   (uniform-c partials)
// CTA = (slice of 256 p, chunk of 16 i). Thread owns p = slice*256 + pg*4 + r
// (r=0..3) and b = bg*8..bg*8+7, pg = tid&63, bg = tid>>6.
// Swizzle: sidx = pg*16 + ((r*4+c) ^ (pg&7))
//   writer: lane-adjacent gi -> consecutive sidx (conflict-free stores)
//   reader: 8-lane phases hit distinct ((r4c^pg)&7) bank groups (conflict-free)
// ---------------------------------------------------------------------------
__global__ void __launch_bounds__(256) k_uhat_fused(const float* __restrict__ x,
                                                    const float* __restrict__ W) {
    const int slice = blockIdx.x;        // 0..7
    const int ch    = blockIdx.y;        // 0..127
    const int tid   = threadIdx.x;
    const int pg    = tid & 63;
    const int bg    = tid >> 6;
    const int b0    = bg * 8;
    const int i0    = ch * ICH;

    __shared__ ulonglong2 Wsm[2][1024];  // swizzled W slices (16 KB each)
    __shared__ ulonglong2 xsm[2][128];   // x[:, i, :] (2 KB each)

    const uint4* W4 = reinterpret_cast<const uint4*>(W);
    const uint4* x4 = reinterpret_cast<const uint4*>(x);

    float s[4][8];
    #pragma unroll
    for (int r = 0; r < 4; ++r)
        #pragma unroll
        for (int bl = 0; bl < 8; ++bl) s[r][bl] = 0.f;

    // stage W[i, slice] + x[:, i, :] into buffer d (conflict-free swizzle)
    #define STAGE(d, i)                                                          \
    do {                                                                         \
        const uint4* wsrc = W4 + ((size_t)(i) * JD + slice * PSL) * 4;           \
        _Pragma("unroll")                                                        \
        for (int q = 0; q < 4; ++q) {                                            \
            const int gi = q * 256 + tid;          /* 0..1023 */                 \
            const int sidx = (gi >> 4) * 16 + ((gi & 15) ^ ((gi >> 4) & 7));     \
            cp_async16(&Wsm[d][sidx], wsrc + gi);                                \
        }                                                                        \
        if (tid < 128) {                                                         \
            const int bb = tid >> 2, k4 = tid & 3;                               \
            cp_async16(&xsm[d][tid], x4 + (size_t)(bb * II + (i)) * 4 + k4);     \
        }                                                                        \
        cp_commit();                                                             \
    } while (0)

    STAGE(0, i0);
    STAGE(1, i0 + 1);

    for (int ii = 0; ii < ICH; ++ii) {
        if (ii == ICH - 1) cp_wait<0>(); else cp_wait<1>();
        __syncthreads();
        const int buf = ii & 1;
        const int i   = i0 + ii;

        // my 4 W rows from swizzled smem (conflict-free)
        ulonglong2 w2[4][4];
        #pragma unroll
        for (int r = 0; r < 4; ++r)
            #pragma unroll
            for (int c = 0; c < 4; ++c)
                w2[r][c] = Wsm[buf][pg * 16 + ((r * 4 + c) ^ (pg & 7))];

        __half* outi = g_uhat + (size_t)i * (BB * JD);

        #pragma unroll 2
        for (int bl = 0; bl < 8; ++bl) {
            const int b = b0 + bl;
            ulonglong2 xv[4];
            #pragma unroll
            for (int c = 0; c < 4; ++c) xv[c] = xsm[buf][b * 4 + c];  // broadcast

            float u[4];
            #pragma unroll
            for (int r = 0; r < 4; ++r) {
                unsigned long long acc = f32x2_mul(w2[r][0].x, xv[0].x);
                acc = f32x2_fma(w2[r][0].y, xv[0].y, acc);
                acc = f32x2_fma(w2[r][1].x, xv[1].x, acc);
                acc = f32x2_fma(w2[r][1].y, xv[1].y, acc);
                acc = f32x2_fma(w2[r][2].x, xv[2].x, acc);
                acc = f32x2_fma(w2[r][2].y, xv[2].y, acc);
                acc = f32x2_fma(w2[r][3].x, xv[3].x, acc);
                acc = f32x2_fma(w2[r][3].y, xv[3].y, acc);
                u[r] = f32x2_hsum(acc);
                s[r][bl] += u[r];
            }
            __half2 h0 = __floats2half2_rn(u[0], u[1]);
            __half2 h1 = __floats2half2_rn(u[2], u[3]);
            uint2 pack;
            pack.x = *reinterpret_cast<unsigned int*>(&h0);
            pack.y = *reinterpret_cast<unsigned int*>(&h1);
            reinterpret_cast<uint2*>(outi + (size_t)b * JD)[slice * 64 + pg] = pack;
        }

        __syncthreads();  // all reads of buf done before restage
        if (ii + 2 < ICH) STAGE(buf, i0 + ii + 2);
    }
    #undef STAGE

    // uniform-c partials (fp32)
    #pragma unroll
    for (int bl = 0; bl < 8; ++bl) {
        const int b = b0 + bl;
        float4* sp = reinterpret_cast<float4*>(g_spart + ((size_t)b * NCH + ch) * JD);
        sp[slice * 64 + pg] = make_float4(s[0][bl], s[1][bl], s[2][bl], s[3][bl]);
    }
}

// ---------------------------------------------------------------------------
// Passes 1 & 2: register-resident u rows, double-buffered cp.async.
// Agreement logits vs g_v (pass 1) or g_vsum = v0+v1 (pass 2, useVsum=1).
// Thread t owns halves 8t..8t+7 of every row (single j = t>>2).
// grid: (B, NCH12), 256 threads.
// ---------------------------------------------------------------------------
__global__ void __launch_bounds__(256, 4) k_pass12(int useVsum) {
    const int b   = blockIdx.x;
    const int ch  = blockIdx.y;
    const int tid = threadIdx.x;
    const int r   = tid >> 6;    // softmax-space row (0..3)
    const int j   = tid & 63;    // softmax-space capsule
    const int wid = tid >> 5;

    __shared__ uint4  ub[2][RR][256];      // 2 x 4 rows x 4KB fp16 (32 KB)
    __shared__ float  lg[JJ * 5];          // [j*5 + rr], padded stride
    __shared__ float  cs[RR][JJ];          // normalized coeffs
    __shared__ float2 ms[8];               // per-warp (max, sum)

    const float* vsrc = useVsum ? g_vsum : g_v;
    float vf[8];
    {
        const float4* gv4 = reinterpret_cast<const float4*>(vsrc + (size_t)b * JD);
        const float4 v0 = gv4[2 * tid], v1 = gv4[2 * tid + 1];
        vf[0] = v0.x; vf[1] = v0.y; vf[2] = v0.z; vf[3] = v0.w;
        vf[4] = v1.x; vf[5] = v1.y; vf[6] = v1.z; vf[7] = v1.w;
    }

    float s[8];
    #pragma unroll
    for (int q = 0; q < 8; ++q) s[q] = 0.f;

    const uint4* grow0 = reinterpret_cast<const uint4*>(
        g_uhat + (size_t)(ch * IPC) * (BB * JD) + (size_t)b * JD);
    const size_t gstride = (size_t)BB * JD / 8;   // uint4 per i row

    #pragma unroll
    for (int rr = 0; rr < RR; ++rr)
        cp_async16(&ub[0][rr][tid], grow0 + (size_t)rr * gstride + tid);
    cp_commit();
    #pragma unroll
    for (int rr = 0; rr < RR; ++rr)
        cp_async16(&ub[1][rr][tid], grow0 + (size_t)(RR + rr) * gstride + tid);
    cp_commit();

    for (int st = 0; st < STEPS; ++st) {
        if (st == STEPS - 1) cp_wait<0>(); else cp_wait<1>();
        const int buf = st & 1;

        uint4 u4[RR];
        #pragma unroll
        for (int rr = 0; rr < RR; ++rr) u4[rr] = ub[buf][rr][tid];

        if (st + 2 < STEPS) {
            const uint4* gr = grow0 + (size_t)(st + 2) * RR * gstride;
            #pragma unroll
            for (int rr = 0; rr < RR; ++rr)
                cp_async16(&ub[buf][rr][tid], gr + (size_t)rr * gstride + tid);
            cp_commit();
        }

        // ---- agreement: per-thread 8-FMA partial dot + quad reduce ----
        float a[RR];
        #pragma unroll
        for (int rr = 0; rr < RR; ++rr) {
            const __half2* h = reinterpret_cast<const __half2*>(&u4[rr]);
            float acc = 0.f;
            #pragma unroll
            for (int m = 0; m < 4; ++m) {
                const float2 f = __half22float2(h[m]);
                acc += f.x * vf[2 * m] + f.y * vf[2 * m + 1];
            }
            acc += __shfl_xor_sync(0xffffffffu, acc, 1);
            acc += __shfl_xor_sync(0xffffffffu, acc, 2);
            a[rr] = acc;
        }
        lg[(tid >> 2) * 5 + (tid & 3)] = a[tid & 3];
        __syncthreads();

        // ---- softmax in (r, j) space ----
        const float araw = lg[j * 5 + r];

        float mw = araw;
        #pragma unroll
        for (int o = 16; o > 0; o >>= 1)
            mw = fmaxf(mw, __shfl_xor_sync(0xffffffffu, mw, o));
        const float e = __expf(araw - mw);
        float sw = e;
        #pragma unroll
        for (int o = 16; o > 0; o >>= 1)
            sw += __shfl_xor_sync(0xffffffffu, sw, o);
        if ((tid & 31) == 0) ms[wid] = make_float2(mw, sw);
        __syncthreads();
        {
            const float2 other = ms[wid ^ 1];
            const float M = fmaxf(mw, other.x);
            const float S = sw * __expf(mw - M) + other.y * __expf(other.x - M);
            cs[r][j] = e * __expf(mw - M) / S;
        }
        __syncthreads();

        // ---- weighted accumulate from registers ----
        #pragma unroll
        for (int rr = 0; rr < RR; ++rr) {
            const float c = cs[rr][tid >> 2];
            const __half2* h = reinterpret_cast<const __half2*>(&u4[rr]);
            #pragma unroll
            for (int m = 0; m < 4; ++m) {
                const float2 f = __half22float2(h[m]);
                s[2 * m]     += c * f.x;
                s[2 * m + 1] += c * f.y;
            }
        }
    }

    // thread t owns p = 8t..8t+7 (float4 store at offset 8t)
    float4* sp = reinterpret_cast<float4*>(g_spart + ((size_t)b * NCH + ch) * JD);
    sp[2 * tid]     = make_float4(s[0], s[1], s[2], s[3]);
    sp[2 * tid + 1] = make_float4(s[4], s[5], s[6], s[7]);
}

// ---------------------------------------------------------------------------
// Squash: one 32-thread block per (b,j). Sums nch chunk partials.
// mode 0: g_v = v, g_vsum = v ; mode 1: g_vsum += v ; mode 2: out = v
// ---------------------------------------------------------------------------
__global__ void k_squash(float prescale, int mode, int nch, float* __restrict__ out) {
    const int row = blockIdx.x;          // b*64 + j
    const int d   = threadIdx.x;
    const int b   = row >> 6;
    const int j   = row & 63;

    const float* sp = g_spart + (size_t)b * NCH * JD + j * 32 + d;
    float sv = 0.f;
    #pragma unroll 8
    for (int ch = 0; ch < nch; ++ch) sv += sp[(size_t)ch * JD];
    sv *= prescale;

    float sq = sv * sv;
    #pragma unroll
    for (int o = 16; o > 0; o >>= 1) sq += __shfl_xor_sync(0xffffffffu, sq, o);

    const float scale = sq / (1.f + sq);
    const float v = scale * sv / sqrtf(sq + 1e-8f);

    const int idx = row * 32 + d;
    if (mode == 0)      { g_v[idx] = v; g_vsum[idx] = v; }
    else if (mode == 1) { g_vsum[idx] += v; }
    else                { out[idx] = v; }
}

// ---------------------------------------------------------------------------
extern "C" void kernel_launch(void* const* d_in, const int* in_sizes, int n_in,
                              void* d_out, int out_size) {
    (void)n_in; (void)out_size;
    const float* x = (const float*)d_in[0];
    const float* W = (const float*)d_in[1];
    if (in_sizes[0] > in_sizes[1]) { const float* t = x; x = W; W = t; }

    float* out = (float*)d_out;

    k_uhat_fused<<<dim3(NSL, NCH), 256>>>(x, W);             // u_hat + s0 partials
    k_squash<<<BB * JJ, 32>>>(1.0f / 64.0f, 0, NCH, nullptr);   // v0 ; vsum = v0

    k_pass12<<<dim3(BB, NCH12), 256>>>(0);                   // logits vs v0
    k_squash<<<BB * JJ, 32>>>(1.0f, 1, NCH12, nullptr);      // vsum = v0+v1

    k_pass12<<<dim3(BB, NCH12), 256>>>(1);                   // logits vs v0+v1
    k_squash<<<BB * JJ, 32>>>(1.0f, 2, NCH12, out);          // v2 -> d_out
}